// round 13
// baseline (speedup 1.0000x reference)
#include <cuda_runtime.h>
#include <cuda_fp16.h>

#define F   128
#define H1  4
#define D   32
#define C1  128
#define NMAX 50176
#define CAP 128         // per-dst edge bucket capacity (Poisson(16): P(>=128) ~ 0)
#define XS  132         // padded smem stride for gemm2 (floats)
#define XT  136         // padded smem stride for gemm1 tf32 tiles (words)

// ---------------- scratch (static device globals; no allocation) -------------
__device__ __align__(16) __half g_h1h[NMAX * C1];   // layer-1 features (fp16)
__device__ __align__(16) float  g_a1 [NMAX * C1];   // layer-1 activated output (fp32)
__device__ __align__(16) float  g_as1[NMAX * H1];
__device__ __align__(16) float  g_ad1[NMAX * H1];
__device__ __align__(16) __half g_h2h[NMAX * D];    // layer-2 features (fp16)
__device__ float g_as2[NMAX];
__device__ float g_ad2[NMAX];
__device__ float g_ps [NMAX];   // dot(emb, Wp[0:32])
__device__ float g_pt [NMAX];   // dot(emb, Wp[32:64])
__device__ int   g_cnt[NMAX];
__device__ __align__(16) int g_col[NMAX * CAP];     // stores s*32 (pre-scaled)

// ---------------- helpers ----------------
__device__ __forceinline__ float lrelu(float e) { return fmaxf(e, 0.2f * e); }
__device__ __forceinline__ float elu_fast(float v) {
    return v > 0.f ? v : (__expf(v) - 1.f);    // abs err <= ~5e-7, exp in (0,1]
}

__device__ __forceinline__ unsigned tf32(float v) {
    unsigned r;
    asm("cvt.rna.tf32.f32 %0, %1;" : "=r"(r) : "f"(v));
    return r;
}
__device__ __forceinline__ void mma_tf32(float c[4], unsigned a0, unsigned a1,
                                         unsigned a2, unsigned a3,
                                         unsigned b0, unsigned b1) {
    asm volatile("mma.sync.aligned.m16n8k8.row.col.f32.tf32.tf32.f32 "
                 "{%0,%1,%2,%3}, {%4,%5,%6,%7}, {%8,%9}, {%0,%1,%2,%3};"
                 : "+f"(c[0]), "+f"(c[1]), "+f"(c[2]), "+f"(c[3])
                 : "r"(a0), "r"(a1), "r"(a2), "r"(a3), "r"(b0), "r"(b1));
}
__device__ __forceinline__ unsigned long long dup2(float x) {
    unsigned long long a;
    asm("mov.b64 %0, {%1, %1};" : "=l"(a) : "f"(x));
    return a;
}
__device__ __forceinline__ void fma2(unsigned long long& d,
                                     unsigned long long a, unsigned long long b) {
    asm("fma.rn.f32x2 %0, %1, %2, %0;" : "+l"(d) : "l"(a), "l"(b));
}
__device__ __forceinline__ float2 unp(unsigned long long v) {
    float2 r;
    asm("mov.b64 {%0, %1}, %2;" : "=f"(r.x), "=f"(r.y) : "l"(v));
    return r;
}
__device__ __forceinline__ float warp_sum(float v) {
#pragma unroll
    for (int o = 16; o; o >>= 1) v += __shfl_xor_sync(0xffffffffu, v, o);
    return v;
}

// ---------------- K1: bucket edges by destination (CSR-lite) ----------------
// stores PRE-SCALED source index s*32 (row offset for h1h uint2 / h2h half).
// runs AFTER gemm1 (which zeroes g_cnt in its prologue).
__global__ void k_scatter(const int* __restrict__ ei, int E, int N) {
    int i = blockIdx.x * blockDim.x + threadIdx.x;
    int Et = E + N;
    if (i >= Et) return;
    int s, t;
    if (i < E) { s = __ldg(ei + i); t = __ldg(ei + E + i); } else { s = t = i - E; }
    int p = atomicAdd(&g_cnt[t], 1);
    if (p < CAP) g_col[t * CAP + p] = s * 32;
}

// ---------------- K2: h1 = x @ W1 via tf32 mma.sync (128-row block) ----------
__global__ void __launch_bounds__(256) k_gemm1(
    const float* __restrict__ x, const float* __restrict__ W1,
    const float* __restrict__ a_s, const float* __restrict__ a_d, int N) {
    extern __shared__ unsigned smu[];
    unsigned* Wt = smu;              // [128][XT] tf32
    unsigned* Xt = smu + 128 * XT;   // [128][XT] tf32; reused as fp32 C after loop
    int tid  = threadIdx.x;
    int row0 = blockIdx.x * 128;

    int zi = blockIdx.x * 256 + tid;
    if (zi < N) g_cnt[zi] = 0;

#pragma unroll
    for (int i = 0; i < 16; i++) {
        int lin = i * 256 + tid;              // float4 index
        int k = lin >> 5, n4 = lin & 31;
        float4 w = ((const float4*)W1)[lin];
        uint4 q = make_uint4(tf32(w.x), tf32(w.y), tf32(w.z), tf32(w.w));
        *(uint4*)(Wt + k * XT + n4 * 4) = q;
    }
#pragma unroll
    for (int i = 0; i < 16; i++) {
        int lin = i * 256 + tid;
        int r = lin >> 5, k4 = lin & 31;
        int row = row0 + r;
        float4 v = make_float4(0.f, 0.f, 0.f, 0.f);
        if (row < N) v = ((const float4*)x)[row * 32 + k4];
        uint4 q = make_uint4(tf32(v.x), tf32(v.y), tf32(v.z), tf32(v.w));
        *(uint4*)(Xt + r * XT + k4 * 4) = q;
    }
    __syncthreads();

    int lane = tid & 31, warp = tid >> 5;
    int g = lane >> 2, t4 = lane & 3;
    int wrow = warp * 16;

    float c[16][4];
#pragma unroll
    for (int n = 0; n < 16; n++) { c[n][0] = c[n][1] = c[n][2] = c[n][3] = 0.f; }

#pragma unroll 2
    for (int k0 = 0; k0 < 128; k0 += 8) {
        unsigned a0 = Xt[(wrow + g)     * XT + k0 + t4];
        unsigned a1 = Xt[(wrow + g + 8) * XT + k0 + t4];
        unsigned a2 = Xt[(wrow + g)     * XT + k0 + t4 + 4];
        unsigned a3 = Xt[(wrow + g + 8) * XT + k0 + t4 + 4];
#pragma unroll
        for (int n = 0; n < 16; n++) {
            unsigned b0 = Wt[(k0 + t4)     * XT + n * 8 + g];
            unsigned b1 = Wt[(k0 + t4 + 4) * XT + n * 8 + g];
            mma_tf32(c[n], a0, a1, a2, a3, b0, b1);
        }
    }
    __syncthreads();

    float* Cs = (float*)Xt;
#pragma unroll
    for (int n = 0; n < 16; n++) {
        *(float2*)(Cs + (wrow + g)     * XT + n * 8 + t4 * 2) = make_float2(c[n][0], c[n][1]);
        *(float2*)(Cs + (wrow + g + 8) * XT + n * 8 + t4 * 2) = make_float2(c[n][2], c[n][3]);
    }
    __syncthreads();

    int tx = tid & 31, ty = tid >> 5;
    float4 sa = ((const float4*)a_s)[tx];
    float4 da = ((const float4*)a_d)[tx];
    int head = tx >> 3;
#pragma unroll
    for (int i = 0; i < 16; i++) {
        int r   = ty * 16 + i;
        int row = row0 + r;
        float4 h = *(const float4*)(Cs + r * XT + tx * 4);
        float ps = h.x * sa.x + h.y * sa.y + h.z * sa.z + h.w * sa.w;
        float pd = h.x * da.x + h.y * da.y + h.z * da.z + h.w * da.w;
#pragma unroll
        for (int o = 4; o; o >>= 1) {
            ps += __shfl_xor_sync(0xffffffffu, ps, o);
            pd += __shfl_xor_sync(0xffffffffu, pd, o);
        }
        if (row < N) {
            __half2 p0 = __floats2half2_rn(h.x, h.y);
            __half2 p1 = __floats2half2_rn(h.z, h.w);
            uint2 pk;
            pk.x = *(unsigned*)&p0;
            pk.y = *(unsigned*)&p1;
            ((uint2*)g_h1h)[row * 32 + tx] = pk;
            if ((tx & 7) == 0) {
                g_as1[row * H1 + head] = ps;
                g_ad1[row * H1 + head] = pd;
            }
        }
    }
}

// ---------------- K3: layer-1 gather-aggregate, smem dense-exp ---------------
// g_col entries are pre-scaled (s*32): uint2 index = sp + lane; as1 row = sp>>3.
__global__ void __launch_bounds__(256) k_agg1(const float* __restrict__ b1, int N) {
    __shared__ float exs[8][H1][CAP];   // 16 KB
    int warp = threadIdx.x >> 5, lane = threadIdx.x & 31;
    int t = blockIdx.x * 8 + warp;
    if (t >= N) return;
    int head = lane >> 3, sub = lane & 7;
    int deg = min(g_cnt[t], CAP);
    const int* cl = g_col + t * CAP;
    float adt = g_ad1[t * H1 + head];

    for (int j0 = 0; j0 < deg; j0 += 8) {
        int idx = j0 + sub;
        if (idx < deg) {
            int sp = cl[idx];
            exs[warp][head][idx] = __expf(lrelu(g_as1[(sp >> 3) + head] + adt));
        }
    }
    __syncwarp();

    const float* eh = exs[warp][head];
    float4 acc = make_float4(0.f, 0.f, 0.f, 0.f);
    float  sum = 0.f;
    int j = 0;
    for (; j + 4 <= deg; j += 4) {
        int4   ss = *(const int4*)(cl + j);
        float4 ev = *(const float4*)(eh + j);
        uint2 p0 = ((const uint2*)g_h1h)[ss.x + lane];
        uint2 p1 = ((const uint2*)g_h1h)[ss.y + lane];
        uint2 p2 = ((const uint2*)g_h1h)[ss.z + lane];
        uint2 p3 = ((const uint2*)g_h1h)[ss.w + lane];
        float2 f0a = __half22float2(*(__half2*)&p0.x), f0b = __half22float2(*(__half2*)&p0.y);
        float2 f1a = __half22float2(*(__half2*)&p1.x), f1b = __half22float2(*(__half2*)&p1.y);
        float2 f2a = __half22float2(*(__half2*)&p2.x), f2b = __half22float2(*(__half2*)&p2.y);
        float2 f3a = __half22float2(*(__half2*)&p3.x), f3b = __half22float2(*(__half2*)&p3.y);
        acc.x += ev.x * f0a.x + ev.y * f1a.x + ev.z * f2a.x + ev.w * f3a.x;
        acc.y += ev.x * f0a.y + ev.y * f1a.y + ev.z * f2a.y + ev.w * f3a.y;
        acc.z += ev.x * f0b.x + ev.y * f1b.x + ev.z * f2b.x + ev.w * f3b.x;
        acc.w += ev.x * f0b.y + ev.y * f1b.y + ev.z * f2b.y + ev.w * f3b.y;
        sum   += (ev.x + ev.y) + (ev.z + ev.w);
    }
    for (; j < deg; j++) {
        int   sp = cl[j];
        float e0 = eh[j];
        uint2 p0 = ((const uint2*)g_h1h)[sp + lane];
        float2 f0a = __half22float2(*(__half2*)&p0.x);
        float2 f0b = __half22float2(*(__half2*)&p0.y);
        acc.x += e0 * f0a.x; acc.y += e0 * f0a.y;
        acc.z += e0 * f0b.x; acc.w += e0 * f0b.y;
        sum += e0;
    }
    float inv = __fdividef(1.f, sum + 1e-16f);
    float4 b = ((const float4*)b1)[lane];
    float4 v;
    v.x = elu_fast(acc.x * inv + b.x);
    v.y = elu_fast(acc.y * inv + b.y);
    v.z = elu_fast(acc.z * inv + b.z);
    v.w = elu_fast(acc.w * inv + b.w);
    ((float4*)g_a1)[t * 32 + lane] = v;
}

// ---------------- K4: h2 = a1 @ W2 (64x32 tile, 4 CTAs/SM) + fused alpha2 ----
// 256 thr; tx = col pair (16), ty = row group (16 x 4 rows). f32x2 FMA.
__global__ void __launch_bounds__(256) k_gemm2(
    const float* __restrict__ W2, const float* __restrict__ a_s,
    const float* __restrict__ a_d, int N) {
    extern __shared__ float sm[];
    float* Ws = sm;               // [128][32]  16 KB
    float* xs = sm + F * D;       // [64][XS]   33 KB
    int tid  = threadIdx.x;
    int row0 = blockIdx.x * 64;

#pragma unroll
    for (int i = 0; i < 4; i++)
        ((float4*)Ws)[i * 256 + tid] = ((const float4*)W2)[i * 256 + tid];
#pragma unroll
    for (int i = 0; i < 8; i++) {
        int lin = i * 256 + tid;
        int k4 = lin & 31, r = lin >> 5;
        int row = row0 + r;
        float4 v = make_float4(0.f, 0.f, 0.f, 0.f);
        if (row < N) v = ((const float4*)g_a1)[row * 32 + k4];
        *(float4*)(xs + r * XS + k4 * 4) = v;
    }
    __syncthreads();

    int tx = tid & 15;            // col pair c0 = tx*2
    int ty = tid >> 4;            // rows ty*4 .. ty*4+3
    int c0 = tx * 2;
    const float* xrow = xs + ty * 4 * XS;
    const float* wcol = Ws + c0;

    unsigned long long acc[4];
#pragma unroll
    for (int i = 0; i < 4; i++) acc[i] = 0ull;

#pragma unroll 4
    for (int k = 0; k < F; k += 4) {
        unsigned long long wp[4];
#pragma unroll
        for (int j = 0; j < 4; j++)
            wp[j] = *(const unsigned long long*)(wcol + (k + j) * D);
#pragma unroll
        for (int i = 0; i < 4; i++) {
            float4 xv = *(const float4*)(xrow + i * XS + k);
            fma2(acc[i], dup2(xv.x), wp[0]);
            fma2(acc[i], dup2(xv.y), wp[1]);
            fma2(acc[i], dup2(xv.z), wp[2]);
            fma2(acc[i], dup2(xv.w), wp[3]);
        }
    }

    float2 sa = *(const float2*)(a_s + c0);
    float2 da = *(const float2*)(a_d + c0);
#pragma unroll
    for (int i = 0; i < 4; i++) {
        int row = row0 + ty * 4 + i;
        float2 hv = unp(acc[i]);
        float ps = hv.x * sa.x + hv.y * sa.y;
        float pd = hv.x * da.x + hv.y * da.y;
#pragma unroll
        for (int o = 8; o; o >>= 1) {   // reduce within 16-lane half-warp
            ps += __shfl_xor_sync(0xffffffffu, ps, o);
            pd += __shfl_xor_sync(0xffffffffu, pd, o);
        }
        if (row < N) {
            __half2 p = __floats2half2_rn(hv.x, hv.y);
            ((unsigned*)g_h2h)[row * 16 + tx] = *(unsigned*)&p;
            if (tx == 0) { g_as2[row] = ps; g_ad2[row] = pd; }
        }
    }
}

// ---------------- K5: layer-2 gather-aggregate + fused rating projection -----
// g_col pre-scaled: h2h index = sp + lane; as2 row = sp>>5.
__global__ void __launch_bounds__(256) k_agg2(
    const float* __restrict__ b2, const float* __restrict__ Wp, int N) {
    __shared__ float exs[8][CAP];   // 4 KB
    int warp = threadIdx.x >> 5, lane = threadIdx.x & 31;
    int t = blockIdx.x * 8 + warp;
    if (t >= N) return;
    float adt = g_ad2[t];
    int   deg = min(g_cnt[t], CAP);
    const int* cl = g_col + t * CAP;

    for (int j0 = 0; j0 < deg; j0 += 32) {
        int idx = j0 + lane;
        if (idx < deg) {
            int sp = cl[idx];
            exs[warp][idx] = __expf(lrelu(g_as2[sp >> 5] + adt));
        }
    }
    __syncwarp();

    const float* eh = exs[warp];
    float acc = 0.f, sum = 0.f;
    int j = 0;
    for (; j + 4 <= deg; j += 4) {
        int4   ss = *(const int4*)(cl + j);
        float4 ev = *(const float4*)(eh + j);
        float h0 = __half2float(g_h2h[ss.x + lane]);
        float h1 = __half2float(g_h2h[ss.y + lane]);
        float h2 = __half2float(g_h2h[ss.z + lane]);
        float h3 = __half2float(g_h2h[ss.w + lane]);
        acc += ev.x * h0 + ev.y * h1 + ev.z * h2 + ev.w * h3;
        sum += (ev.x + ev.y) + (ev.z + ev.w);
    }
    for (; j < deg; j++) {
        int   sp = cl[j];
        float e0 = eh[j];
        acc += e0 * __half2float(g_h2h[sp + lane]);
        sum += e0;
    }
    float v = acc * __fdividef(1.f, sum + 1e-16f) + b2[lane];
    float ps = warp_sum(v * Wp[lane]);
    float pt = warp_sum(v * Wp[D + lane]);
    if (lane == 0) { g_ps[t] = ps; g_pt[t] = pt; }
}

// ---------------- K6: edge rating = ps[src] + pt[dst] + bp (thread/edge) -----
__global__ void __launch_bounds__(256) k_pred(
    const int* __restrict__ ei, const float* __restrict__ bp,
    float* __restrict__ out, int E) {
    int e = blockIdx.x * blockDim.x + threadIdx.x;
    if (e >= E) return;
    int s = __ldg(ei + e), t = __ldg(ei + E + e);
    out[e] = g_ps[s] + g_pt[t] + bp[0];
}

// ---------------- launch ----------------
extern "C" void kernel_launch(void* const* d_in, const int* in_sizes, int n_in,
                              void* d_out, int out_size) {
    const float* x   = (const float*)d_in[0];
    const int*   ei  = (const int*)  d_in[1];
    const float* W1  = (const float*)d_in[2];
    const float* as1 = (const float*)d_in[3];
    const float* ad1 = (const float*)d_in[4];
    const float* b1  = (const float*)d_in[5];
    const float* W2  = (const float*)d_in[6];
    const float* as2 = (const float*)d_in[7];
    const float* ad2 = (const float*)d_in[8];
    const float* b2  = (const float*)d_in[9];
    const float* Wp  = (const float*)d_in[10];
    const float* bp  = (const float*)d_in[11];
    float*       out = (float*)d_out;

    int N  = in_sizes[0] / F;
    int E  = in_sizes[1] / 2;
    int Et = E + N;
    if (N > NMAX) return;

    int smem1 = 2 * 128 * XT * (int)sizeof(unsigned);   // 139264
    int smem2 = (F * D + 64 * XS) * (int)sizeof(float); // 50176
    cudaFuncSetAttribute(k_gemm1, cudaFuncAttributeMaxDynamicSharedMemorySize, smem1);
    cudaFuncSetAttribute(k_gemm2, cudaFuncAttributeMaxDynamicSharedMemorySize, smem2);

    k_gemm1  <<<(N + 127) / 128, 256, smem1>>>(x, W1, as1, ad1, N);  // also zeroes g_cnt
    k_scatter<<<(Et + 255) / 256, 256>>>(ei, E, N);
    k_agg1   <<<(N + 7) / 8, 256>>>(b1, N);
    k_gemm2  <<<(N + 63) / 64, 256, smem2>>>(W2, as2, ad2, N);
    k_agg2   <<<(N + 7) / 8, 256>>>(b2, Wp, N);
    k_pred   <<<(E + 255) / 256, 256>>>(ei, bp, out, E);
}

// round 14
// speedup vs baseline: 1.0488x; 1.0488x over previous
#include <cuda_runtime.h>
#include <cuda_fp16.h>

#define F   128
#define H1  4
#define D   32
#define C1  128
#define NMAX 50176
#define CAP 128         // per-dst edge bucket capacity (Poisson(16): P(>=128) ~ 0)
#define XT  136         // padded smem stride for gemm1 tf32 tiles (words)
#define XA  132         // gemm2 A-tile stride (words): conflict-free A frags
#define WB  40          // gemm2 B-tile stride (words): conflict-free B frags

// ---------------- scratch (static device globals; no allocation) -------------
__device__ __align__(16) __half g_h1h[NMAX * C1];   // layer-1 features (fp16)
__device__ __align__(16) float  g_a1 [NMAX * C1];   // layer-1 activated output (fp32)
__device__ __align__(16) float  g_as1[NMAX * H1];
__device__ __align__(16) float  g_ad1[NMAX * H1];
__device__ __align__(16) __half g_h2h[NMAX * D];    // layer-2 features (fp16)
__device__ float g_as2[NMAX];
__device__ float g_ad2[NMAX];
__device__ float g_ps [NMAX];   // dot(emb, Wp[0:32])
__device__ float g_pt [NMAX];   // dot(emb, Wp[32:64])
__device__ int   g_cnt[NMAX];
__device__ __align__(16) int g_col[NMAX * CAP];     // stores s*32 (pre-scaled)

// ---------------- helpers ----------------
__device__ __forceinline__ float lrelu(float e) { return fmaxf(e, 0.2f * e); }
__device__ __forceinline__ float elu_fast(float v) {
    return v > 0.f ? v : (__expf(v) - 1.f);    // abs err <= ~5e-7, exp in (0,1]
}

__device__ __forceinline__ unsigned tf32(float v) {
    unsigned r;
    asm("cvt.rna.tf32.f32 %0, %1;" : "=r"(r) : "f"(v));
    return r;
}
__device__ __forceinline__ void mma_tf32(float c[4], unsigned a0, unsigned a1,
                                         unsigned a2, unsigned a3,
                                         unsigned b0, unsigned b1) {
    asm volatile("mma.sync.aligned.m16n8k8.row.col.f32.tf32.tf32.f32 "
                 "{%0,%1,%2,%3}, {%4,%5,%6,%7}, {%8,%9}, {%0,%1,%2,%3};"
                 : "+f"(c[0]), "+f"(c[1]), "+f"(c[2]), "+f"(c[3])
                 : "r"(a0), "r"(a1), "r"(a2), "r"(a3), "r"(b0), "r"(b1));
}
__device__ __forceinline__ float warp_sum(float v) {
#pragma unroll
    for (int o = 16; o; o >>= 1) v += __shfl_xor_sync(0xffffffffu, v, o);
    return v;
}

// ---------------- K1: bucket edges by destination (CSR-lite) ----------------
// stores PRE-SCALED source index s*32; runs AFTER gemm1 (zeroes g_cnt there).
__global__ void k_scatter(const int* __restrict__ ei, int E, int N) {
    int i = blockIdx.x * blockDim.x + threadIdx.x;
    int Et = E + N;
    if (i >= Et) return;
    int s, t;
    if (i < E) { s = __ldg(ei + i); t = __ldg(ei + E + i); } else { s = t = i - E; }
    int p = atomicAdd(&g_cnt[t], 1);
    if (p < CAP) g_col[t * CAP + p] = s * 32;
}

// ---------------- K2: h1 = x @ W1 via tf32 mma.sync (128-row block) ----------
__global__ void __launch_bounds__(256) k_gemm1(
    const float* __restrict__ x, const float* __restrict__ W1,
    const float* __restrict__ a_s, const float* __restrict__ a_d, int N) {
    extern __shared__ unsigned smu[];
    unsigned* Wt = smu;              // [128][XT] tf32
    unsigned* Xt = smu + 128 * XT;   // [128][XT] tf32; reused as fp32 C after loop
    int tid  = threadIdx.x;
    int row0 = blockIdx.x * 128;

    int zi = blockIdx.x * 256 + tid;
    if (zi < N) g_cnt[zi] = 0;

#pragma unroll
    for (int i = 0; i < 16; i++) {
        int lin = i * 256 + tid;              // float4 index
        int k = lin >> 5, n4 = lin & 31;
        float4 w = ((const float4*)W1)[lin];
        uint4 q = make_uint4(tf32(w.x), tf32(w.y), tf32(w.z), tf32(w.w));
        *(uint4*)(Wt + k * XT + n4 * 4) = q;
    }
#pragma unroll
    for (int i = 0; i < 16; i++) {
        int lin = i * 256 + tid;
        int r = lin >> 5, k4 = lin & 31;
        int row = row0 + r;
        float4 v = make_float4(0.f, 0.f, 0.f, 0.f);
        if (row < N) v = ((const float4*)x)[row * 32 + k4];
        uint4 q = make_uint4(tf32(v.x), tf32(v.y), tf32(v.z), tf32(v.w));
        *(uint4*)(Xt + r * XT + k4 * 4) = q;
    }
    __syncthreads();

    int lane = tid & 31, warp = tid >> 5;
    int g = lane >> 2, t4 = lane & 3;
    int wrow = warp * 16;

    float c[16][4];
#pragma unroll
    for (int n = 0; n < 16; n++) { c[n][0] = c[n][1] = c[n][2] = c[n][3] = 0.f; }

#pragma unroll 2
    for (int k0 = 0; k0 < 128; k0 += 8) {
        unsigned a0 = Xt[(wrow + g)     * XT + k0 + t4];
        unsigned a1 = Xt[(wrow + g + 8) * XT + k0 + t4];
        unsigned a2 = Xt[(wrow + g)     * XT + k0 + t4 + 4];
        unsigned a3 = Xt[(wrow + g + 8) * XT + k0 + t4 + 4];
#pragma unroll
        for (int n = 0; n < 16; n++) {
            unsigned b0 = Wt[(k0 + t4)     * XT + n * 8 + g];
            unsigned b1 = Wt[(k0 + t4 + 4) * XT + n * 8 + g];
            mma_tf32(c[n], a0, a1, a2, a3, b0, b1);
        }
    }
    __syncthreads();

    float* Cs = (float*)Xt;
#pragma unroll
    for (int n = 0; n < 16; n++) {
        *(float2*)(Cs + (wrow + g)     * XT + n * 8 + t4 * 2) = make_float2(c[n][0], c[n][1]);
        *(float2*)(Cs + (wrow + g + 8) * XT + n * 8 + t4 * 2) = make_float2(c[n][2], c[n][3]);
    }
    __syncthreads();

    int tx = tid & 31, ty = tid >> 5;
    float4 sa = ((const float4*)a_s)[tx];
    float4 da = ((const float4*)a_d)[tx];
    int head = tx >> 3;
#pragma unroll
    for (int i = 0; i < 16; i++) {
        int r   = ty * 16 + i;
        int row = row0 + r;
        float4 h = *(const float4*)(Cs + r * XT + tx * 4);
        float ps = h.x * sa.x + h.y * sa.y + h.z * sa.z + h.w * sa.w;
        float pd = h.x * da.x + h.y * da.y + h.z * da.z + h.w * da.w;
#pragma unroll
        for (int o = 4; o; o >>= 1) {
            ps += __shfl_xor_sync(0xffffffffu, ps, o);
            pd += __shfl_xor_sync(0xffffffffu, pd, o);
        }
        if (row < N) {
            __half2 p0 = __floats2half2_rn(h.x, h.y);
            __half2 p1 = __floats2half2_rn(h.z, h.w);
            uint2 pk;
            pk.x = *(unsigned*)&p0;
            pk.y = *(unsigned*)&p1;
            ((uint2*)g_h1h)[row * 32 + tx] = pk;
            if ((tx & 7) == 0) {
                g_as1[row * H1 + head] = ps;
                g_ad1[row * H1 + head] = pd;
            }
        }
    }
}

// ---------------- K3: layer-1 gather-aggregate, smem dense-exp ---------------
__global__ void __launch_bounds__(256) k_agg1(const float* __restrict__ b1, int N) {
    __shared__ float exs[8][H1][CAP];   // 16 KB
    int warp = threadIdx.x >> 5, lane = threadIdx.x & 31;
    int t = blockIdx.x * 8 + warp;
    if (t >= N) return;
    int head = lane >> 3, sub = lane & 7;
    int deg = min(g_cnt[t], CAP);
    const int* cl = g_col + t * CAP;
    float adt = g_ad1[t * H1 + head];

    for (int j0 = 0; j0 < deg; j0 += 8) {
        int idx = j0 + sub;
        if (idx < deg) {
            int sp = cl[idx];
            exs[warp][head][idx] = __expf(lrelu(g_as1[(sp >> 3) + head] + adt));
        }
    }
    __syncwarp();

    const float* eh = exs[warp][head];
    float4 acc = make_float4(0.f, 0.f, 0.f, 0.f);
    float  sum = 0.f;
    int j = 0;
    for (; j + 4 <= deg; j += 4) {
        int4   ss = *(const int4*)(cl + j);
        float4 ev = *(const float4*)(eh + j);
        uint2 p0 = ((const uint2*)g_h1h)[ss.x + lane];
        uint2 p1 = ((const uint2*)g_h1h)[ss.y + lane];
        uint2 p2 = ((const uint2*)g_h1h)[ss.z + lane];
        uint2 p3 = ((const uint2*)g_h1h)[ss.w + lane];
        float2 f0a = __half22float2(*(__half2*)&p0.x), f0b = __half22float2(*(__half2*)&p0.y);
        float2 f1a = __half22float2(*(__half2*)&p1.x), f1b = __half22float2(*(__half2*)&p1.y);
        float2 f2a = __half22float2(*(__half2*)&p2.x), f2b = __half22float2(*(__half2*)&p2.y);
        float2 f3a = __half22float2(*(__half2*)&p3.x), f3b = __half22float2(*(__half2*)&p3.y);
        acc.x += ev.x * f0a.x + ev.y * f1a.x + ev.z * f2a.x + ev.w * f3a.x;
        acc.y += ev.x * f0a.y + ev.y * f1a.y + ev.z * f2a.y + ev.w * f3a.y;
        acc.z += ev.x * f0b.x + ev.y * f1b.x + ev.z * f2b.x + ev.w * f3b.x;
        acc.w += ev.x * f0b.y + ev.y * f1b.y + ev.z * f2b.y + ev.w * f3b.y;
        sum   += (ev.x + ev.y) + (ev.z + ev.w);
    }
    for (; j < deg; j++) {
        int   sp = cl[j];
        float e0 = eh[j];
        uint2 p0 = ((const uint2*)g_h1h)[sp + lane];
        float2 f0a = __half22float2(*(__half2*)&p0.x);
        float2 f0b = __half22float2(*(__half2*)&p0.y);
        acc.x += e0 * f0a.x; acc.y += e0 * f0a.y;
        acc.z += e0 * f0b.x; acc.w += e0 * f0b.y;
        sum += e0;
    }
    float inv = __fdividef(1.f, sum + 1e-16f);
    float4 b = ((const float4*)b1)[lane];
    float4 v;
    v.x = elu_fast(acc.x * inv + b.x);
    v.y = elu_fast(acc.y * inv + b.y);
    v.z = elu_fast(acc.z * inv + b.z);
    v.w = elu_fast(acc.w * inv + b.w);
    ((float4*)g_a1)[t * 32 + lane] = v;
}

// ---------------- K4: h2 = a1 @ W2 via tf32 mma.sync (64-row block) ----------
// 8 warps: rw = warp&3 -> rows rw*16..+15; nh = warp>>2 -> cols nh*16..+15.
// A staged tf32 stride XA=132 (conflict-free A frags); W2 stride WB=40
// (conflict-free B frags). 54 KB smem -> 4 CTAs/SM.
__global__ void __launch_bounds__(256) k_gemm2(
    const float* __restrict__ W2, const float* __restrict__ a_s,
    const float* __restrict__ a_d, int N) {
    extern __shared__ unsigned sm2[];
    unsigned* Wt = sm2;              // [128][WB] tf32
    unsigned* Xt = sm2 + 128 * WB;   // [64][XA] tf32; reused as fp32 C
    int tid  = threadIdx.x;
    int row0 = blockIdx.x * 64;

    // stage W2 (128x32) as tf32
#pragma unroll
    for (int i = 0; i < 4; i++) {
        int lin = i * 256 + tid;              // float4 index (1024 total)
        int k = lin >> 3, n4 = lin & 7;
        float4 w = ((const float4*)W2)[lin];
        uint4 q = make_uint4(tf32(w.x), tf32(w.y), tf32(w.z), tf32(w.w));
        *(uint4*)(Wt + k * WB + n4 * 4) = q;
    }
    // stage a1 rows as tf32
#pragma unroll
    for (int i = 0; i < 8; i++) {
        int lin = i * 256 + tid;
        int r = lin >> 5, k4 = lin & 31;
        int row = row0 + r;
        float4 v = make_float4(0.f, 0.f, 0.f, 0.f);
        if (row < N) v = ((const float4*)g_a1)[row * 32 + k4];
        uint4 q = make_uint4(tf32(v.x), tf32(v.y), tf32(v.z), tf32(v.w));
        *(uint4*)(Xt + r * XA + k4 * 4) = q;
    }
    __syncthreads();

    int lane = tid & 31, warp = tid >> 5;
    int g = lane >> 2, t4 = lane & 3;
    int rw16 = (warp & 3) * 16;
    int nh   = (warp >> 2) * 16;

    float c[2][4];
    c[0][0] = c[0][1] = c[0][2] = c[0][3] = 0.f;
    c[1][0] = c[1][1] = c[1][2] = c[1][3] = 0.f;

#pragma unroll 4
    for (int k0 = 0; k0 < 128; k0 += 8) {
        unsigned a0 = Xt[(rw16 + g)     * XA + k0 + t4];
        unsigned a1 = Xt[(rw16 + g + 8) * XA + k0 + t4];
        unsigned a2 = Xt[(rw16 + g)     * XA + k0 + t4 + 4];
        unsigned a3 = Xt[(rw16 + g + 8) * XA + k0 + t4 + 4];
#pragma unroll
        for (int n = 0; n < 2; n++) {
            unsigned b0 = Wt[(k0 + t4)     * WB + nh + n * 8 + g];
            unsigned b1 = Wt[(k0 + t4 + 4) * WB + nh + n * 8 + g];
            mma_tf32(c[n], a0, a1, a2, a3, b0, b1);
        }
    }
    __syncthreads();                 // done reading Xt

    float* Cs = (float*)Xt;          // reuse as [64][XA] fp32
#pragma unroll
    for (int n = 0; n < 2; n++) {
        int col = nh + n * 8 + t4 * 2;
        *(float2*)(Cs + (rw16 + g)     * XA + col) = make_float2(c[n][0], c[n][1]);
        *(float2*)(Cs + (rw16 + g + 8) * XA + col) = make_float2(c[n][2], c[n][3]);
    }
    __syncthreads();

    // epilogue: warp w2 covers rows w2*8..+7, lane = col
    int w2 = tid >> 5;
    float sa = a_s[lane], da = a_d[lane];
#pragma unroll
    for (int i = 0; i < 8; i++) {
        int r   = w2 * 8 + i;
        int row = row0 + r;
        float v = Cs[r * XA + lane];
        float ps = warp_sum(v * sa);
        float pd = warp_sum(v * da);
        if (row < N) {
            g_h2h[row * D + lane] = __float2half(v);
            if (lane == 0) { g_as2[row] = ps; g_ad2[row] = pd; }
        }
    }
}

// ---------------- K5: layer-2 gather-aggregate + fused rating projection -----
__global__ void __launch_bounds__(256) k_agg2(
    const float* __restrict__ b2, const float* __restrict__ Wp, int N) {
    __shared__ float exs[8][CAP];   // 4 KB
    int warp = threadIdx.x >> 5, lane = threadIdx.x & 31;
    int t = blockIdx.x * 8 + warp;
    if (t >= N) return;
    float adt = g_ad2[t];
    int   deg = min(g_cnt[t], CAP);
    const int* cl = g_col + t * CAP;

    for (int j0 = 0; j0 < deg; j0 += 32) {
        int idx = j0 + lane;
        if (idx < deg) {
            int sp = cl[idx];
            exs[warp][idx] = __expf(lrelu(g_as2[sp >> 5] + adt));
        }
    }
    __syncwarp();

    const float* eh = exs[warp];
    float acc = 0.f, sum = 0.f;
    int j = 0;
    for (; j + 4 <= deg; j += 4) {
        int4   ss = *(const int4*)(cl + j);
        float4 ev = *(const float4*)(eh + j);
        float h0 = __half2float(g_h2h[ss.x + lane]);
        float h1 = __half2float(g_h2h[ss.y + lane]);
        float h2 = __half2float(g_h2h[ss.z + lane]);
        float h3 = __half2float(g_h2h[ss.w + lane]);
        acc += ev.x * h0 + ev.y * h1 + ev.z * h2 + ev.w * h3;
        sum += (ev.x + ev.y) + (ev.z + ev.w);
    }
    for (; j < deg; j++) {
        int   sp = cl[j];
        float e0 = eh[j];
        acc += e0 * __half2float(g_h2h[sp + lane]);
        sum += e0;
    }
    float v = acc * __fdividef(1.f, sum + 1e-16f) + b2[lane];
    float ps = warp_sum(v * Wp[lane]);
    float pt = warp_sum(v * Wp[D + lane]);
    if (lane == 0) { g_ps[t] = ps; g_pt[t] = pt; }
}

// ---------------- K6: edge rating = ps[src] + pt[dst] + bp (thread/edge) -----
__global__ void __launch_bounds__(256) k_pred(
    const int* __restrict__ ei, const float* __restrict__ bp,
    float* __restrict__ out, int E) {
    int e = blockIdx.x * blockDim.x + threadIdx.x;
    if (e >= E) return;
    int s = __ldg(ei + e), t = __ldg(ei + E + e);
    out[e] = g_ps[s] + g_pt[t] + bp[0];
}

// ---------------- launch ----------------
extern "C" void kernel_launch(void* const* d_in, const int* in_sizes, int n_in,
                              void* d_out, int out_size) {
    const float* x   = (const float*)d_in[0];
    const int*   ei  = (const int*)  d_in[1];
    const float* W1  = (const float*)d_in[2];
    const float* as1 = (const float*)d_in[3];
    const float* ad1 = (const float*)d_in[4];
    const float* b1  = (const float*)d_in[5];
    const float* W2  = (const float*)d_in[6];
    const float* as2 = (const float*)d_in[7];
    const float* ad2 = (const float*)d_in[8];
    const float* b2  = (const float*)d_in[9];
    const float* Wp  = (const float*)d_in[10];
    const float* bp  = (const float*)d_in[11];
    float*       out = (float*)d_out;

    int N  = in_sizes[0] / F;
    int E  = in_sizes[1] / 2;
    int Et = E + N;
    if (N > NMAX) return;

    int smem1 = 2 * 128 * XT * (int)sizeof(unsigned);           // 139264
    int smem2 = (128 * WB + 64 * XA) * (int)sizeof(unsigned);   // 54272
    cudaFuncSetAttribute(k_gemm1, cudaFuncAttributeMaxDynamicSharedMemorySize, smem1);
    cudaFuncSetAttribute(k_gemm2, cudaFuncAttributeMaxDynamicSharedMemorySize, smem2);

    k_gemm1  <<<(N + 127) / 128, 256, smem1>>>(x, W1, as1, ad1, N);  // also zeroes g_cnt
    k_scatter<<<(Et + 255) / 256, 256>>>(ei, E, N);
    k_agg1   <<<(N + 7) / 8, 256>>>(b1, N);
    k_gemm2  <<<(N + 63) / 64, 256, smem2>>>(W2, as2, ad2, N);
    k_agg2   <<<(N + 7) / 8, 256>>>(b2, Wp, N);
    k_pred   <<<(E + 255) / 256, 256>>>(ei, bp, out, E);
}

// round 15
// speedup vs baseline: 1.1002x; 1.0489x over previous
#include <cuda_runtime.h>
#include <cuda_fp16.h>

#define F   128
#define H1  4
#define D   32
#define C1  128
#define NMAX 50176
#define CAP 128         // per-dst edge bucket capacity (Poisson(16): P(>=128) ~ 0)
#define XT  136         // gemm1 tf32 tile stride (words)
#define AS2 136         // gemm2 A-tile stride (halves): conflict-free frags
#define BS2 136         // gemm2 B-tile stride (halves)
#define CS2 36          // gemm2 C-tile stride (fp32 words)

// ---------------- scratch (static device globals; no allocation) -------------
__device__ __align__(16) __half g_h1h[NMAX * C1];   // layer-1 features (fp16)
__device__ __align__(16) __half g_a1h[NMAX * C1];   // layer-1 activated output (fp16)
__device__ __align__(16) float  g_as1[NMAX * H1];
__device__ __align__(16) float  g_ad1[NMAX * H1];
__device__ __align__(16) __half g_h2h[NMAX * D];    // layer-2 features (fp16)
__device__ float g_as2[NMAX];
__device__ float g_ad2[NMAX];
__device__ float g_ps [NMAX];   // dot(emb, Wp[0:32])
__device__ float g_pt [NMAX];   // dot(emb, Wp[32:64])
__device__ int   g_cnt[NMAX];
__device__ __align__(16) int g_col[NMAX * CAP];     // stores s*32 (pre-scaled)

// ---------------- helpers ----------------
__device__ __forceinline__ float lrelu(float e) { return fmaxf(e, 0.2f * e); }
__device__ __forceinline__ float elu_fast(float v) {
    return v > 0.f ? v : (__expf(v) - 1.f);
}

__device__ __forceinline__ unsigned tf32(float v) {
    unsigned r;
    asm("cvt.rna.tf32.f32 %0, %1;" : "=r"(r) : "f"(v));
    return r;
}
__device__ __forceinline__ void mma_tf32(float c[4], unsigned a0, unsigned a1,
                                         unsigned a2, unsigned a3,
                                         unsigned b0, unsigned b1) {
    asm volatile("mma.sync.aligned.m16n8k8.row.col.f32.tf32.tf32.f32 "
                 "{%0,%1,%2,%3}, {%4,%5,%6,%7}, {%8,%9}, {%0,%1,%2,%3};"
                 : "+f"(c[0]), "+f"(c[1]), "+f"(c[2]), "+f"(c[3])
                 : "r"(a0), "r"(a1), "r"(a2), "r"(a3), "r"(b0), "r"(b1));
}
__device__ __forceinline__ void mma_f16(float c[4], unsigned a0, unsigned a1,
                                        unsigned a2, unsigned a3,
                                        unsigned b0, unsigned b1) {
    asm volatile("mma.sync.aligned.m16n8k16.row.col.f32.f16.f16.f32 "
                 "{%0,%1,%2,%3}, {%4,%5,%6,%7}, {%8,%9}, {%0,%1,%2,%3};"
                 : "+f"(c[0]), "+f"(c[1]), "+f"(c[2]), "+f"(c[3])
                 : "r"(a0), "r"(a1), "r"(a2), "r"(a3), "r"(b0), "r"(b1));
}
__device__ __forceinline__ float warp_sum(float v) {
#pragma unroll
    for (int o = 16; o; o >>= 1) v += __shfl_xor_sync(0xffffffffu, v, o);
    return v;
}

// ---------------- K1: bucket edges by destination (CSR-lite) ----------------
__global__ void k_scatter(const int* __restrict__ ei, int E, int N) {
    int i = blockIdx.x * blockDim.x + threadIdx.x;
    int Et = E + N;
    if (i >= Et) return;
    int s, t;
    if (i < E) { s = __ldg(ei + i); t = __ldg(ei + E + i); } else { s = t = i - E; }
    int p = atomicAdd(&g_cnt[t], 1);
    if (p < CAP) g_col[t * CAP + p] = s * 32;
}

// ---------------- K2: h1 = x @ W1 via tf32 mma.sync (128-row block) ----------
__global__ void __launch_bounds__(256) k_gemm1(
    const float* __restrict__ x, const float* __restrict__ W1,
    const float* __restrict__ a_s, const float* __restrict__ a_d, int N) {
    extern __shared__ unsigned smu[];
    unsigned* Wt = smu;              // [128][XT] tf32
    unsigned* Xt = smu + 128 * XT;   // [128][XT] tf32; reused as fp32 C after loop
    int tid  = threadIdx.x;
    int row0 = blockIdx.x * 128;

    int zi = blockIdx.x * 256 + tid;
    if (zi < N) g_cnt[zi] = 0;

#pragma unroll
    for (int i = 0; i < 16; i++) {
        int lin = i * 256 + tid;              // float4 index
        int k = lin >> 5, n4 = lin & 31;
        float4 w = ((const float4*)W1)[lin];
        uint4 q = make_uint4(tf32(w.x), tf32(w.y), tf32(w.z), tf32(w.w));
        *(uint4*)(Wt + k * XT + n4 * 4) = q;
    }
#pragma unroll
    for (int i = 0; i < 16; i++) {
        int lin = i * 256 + tid;
        int r = lin >> 5, k4 = lin & 31;
        int row = row0 + r;
        float4 v = make_float4(0.f, 0.f, 0.f, 0.f);
        if (row < N) v = ((const float4*)x)[row * 32 + k4];
        uint4 q = make_uint4(tf32(v.x), tf32(v.y), tf32(v.z), tf32(v.w));
        *(uint4*)(Xt + r * XT + k4 * 4) = q;
    }
    __syncthreads();

    int lane = tid & 31, warp = tid >> 5;
    int g = lane >> 2, t4 = lane & 3;
    int wrow = warp * 16;

    float c[16][4];
#pragma unroll
    for (int n = 0; n < 16; n++) { c[n][0] = c[n][1] = c[n][2] = c[n][3] = 0.f; }

#pragma unroll 2
    for (int k0 = 0; k0 < 128; k0 += 8) {
        unsigned a0 = Xt[(wrow + g)     * XT + k0 + t4];
        unsigned a1 = Xt[(wrow + g + 8) * XT + k0 + t4];
        unsigned a2 = Xt[(wrow + g)     * XT + k0 + t4 + 4];
        unsigned a3 = Xt[(wrow + g + 8) * XT + k0 + t4 + 4];
#pragma unroll
        for (int n = 0; n < 16; n++) {
            unsigned b0 = Wt[(k0 + t4)     * XT + n * 8 + g];
            unsigned b1 = Wt[(k0 + t4 + 4) * XT + n * 8 + g];
            mma_tf32(c[n], a0, a1, a2, a3, b0, b1);
        }
    }
    __syncthreads();

    float* Cs = (float*)Xt;
#pragma unroll
    for (int n = 0; n < 16; n++) {
        *(float2*)(Cs + (wrow + g)     * XT + n * 8 + t4 * 2) = make_float2(c[n][0], c[n][1]);
        *(float2*)(Cs + (wrow + g + 8) * XT + n * 8 + t4 * 2) = make_float2(c[n][2], c[n][3]);
    }
    __syncthreads();

    int tx = tid & 31, ty = tid >> 5;
    float4 sa = ((const float4*)a_s)[tx];
    float4 da = ((const float4*)a_d)[tx];
    int head = tx >> 3;
#pragma unroll
    for (int i = 0; i < 16; i++) {
        int r   = ty * 16 + i;
        int row = row0 + r;
        float4 h = *(const float4*)(Cs + r * XT + tx * 4);
        float ps = h.x * sa.x + h.y * sa.y + h.z * sa.z + h.w * sa.w;
        float pd = h.x * da.x + h.y * da.y + h.z * da.z + h.w * da.w;
#pragma unroll
        for (int o = 4; o; o >>= 1) {
            ps += __shfl_xor_sync(0xffffffffu, ps, o);
            pd += __shfl_xor_sync(0xffffffffu, pd, o);
        }
        if (row < N) {
            __half2 p0 = __floats2half2_rn(h.x, h.y);
            __half2 p1 = __floats2half2_rn(h.z, h.w);
            uint2 pk;
            pk.x = *(unsigned*)&p0;
            pk.y = *(unsigned*)&p1;
            ((uint2*)g_h1h)[row * 32 + tx] = pk;
            if ((tx & 7) == 0) {
                g_as1[row * H1 + head] = ps;
                g_ad1[row * H1 + head] = pd;
            }
        }
    }
}

// ---------------- K3: layer-1 gather-aggregate, smem dense-exp ---------------
// output written as fp16 (half4 per lane) for the fp16 gemm2.
__global__ void __launch_bounds__(256) k_agg1(const float* __restrict__ b1, int N) {
    __shared__ float exs[8][H1][CAP];   // 16 KB
    int warp = threadIdx.x >> 5, lane = threadIdx.x & 31;
    int t = blockIdx.x * 8 + warp;
    if (t >= N) return;
    int head = lane >> 3, sub = lane & 7;
    int deg = min(g_cnt[t], CAP);
    const int* cl = g_col + t * CAP;
    float adt = g_ad1[t * H1 + head];

    for (int j0 = 0; j0 < deg; j0 += 8) {
        int idx = j0 + sub;
        if (idx < deg) {
            int sp = cl[idx];
            exs[warp][head][idx] = __expf(lrelu(g_as1[(sp >> 3) + head] + adt));
        }
    }
    __syncwarp();

    const float* eh = exs[warp][head];
    float4 acc = make_float4(0.f, 0.f, 0.f, 0.f);
    float  sum = 0.f;
    int j = 0;
    for (; j + 4 <= deg; j += 4) {
        int4   ss = *(const int4*)(cl + j);
        float4 ev = *(const float4*)(eh + j);
        uint2 p0 = ((const uint2*)g_h1h)[ss.x + lane];
        uint2 p1 = ((const uint2*)g_h1h)[ss.y + lane];
        uint2 p2 = ((const uint2*)g_h1h)[ss.z + lane];
        uint2 p3 = ((const uint2*)g_h1h)[ss.w + lane];
        float2 f0a = __half22float2(*(__half2*)&p0.x), f0b = __half22float2(*(__half2*)&p0.y);
        float2 f1a = __half22float2(*(__half2*)&p1.x), f1b = __half22float2(*(__half2*)&p1.y);
        float2 f2a = __half22float2(*(__half2*)&p2.x), f2b = __half22float2(*(__half2*)&p2.y);
        float2 f3a = __half22float2(*(__half2*)&p3.x), f3b = __half22float2(*(__half2*)&p3.y);
        acc.x += ev.x * f0a.x + ev.y * f1a.x + ev.z * f2a.x + ev.w * f3a.x;
        acc.y += ev.x * f0a.y + ev.y * f1a.y + ev.z * f2a.y + ev.w * f3a.y;
        acc.z += ev.x * f0b.x + ev.y * f1b.x + ev.z * f2b.x + ev.w * f3b.x;
        acc.w += ev.x * f0b.y + ev.y * f1b.y + ev.z * f2b.y + ev.w * f3b.y;
        sum   += (ev.x + ev.y) + (ev.z + ev.w);
    }
    for (; j < deg; j++) {
        int   sp = cl[j];
        float e0 = eh[j];
        uint2 p0 = ((const uint2*)g_h1h)[sp + lane];
        float2 f0a = __half22float2(*(__half2*)&p0.x);
        float2 f0b = __half22float2(*(__half2*)&p0.y);
        acc.x += e0 * f0a.x; acc.y += e0 * f0a.y;
        acc.z += e0 * f0b.x; acc.w += e0 * f0b.y;
        sum += e0;
    }
    float inv = __fdividef(1.f, sum + 1e-16f);
    float4 b = ((const float4*)b1)[lane];
    float vx = elu_fast(acc.x * inv + b.x);
    float vy = elu_fast(acc.y * inv + b.y);
    float vz = elu_fast(acc.z * inv + b.z);
    float vw = elu_fast(acc.w * inv + b.w);
    __half2 q0 = __floats2half2_rn(vx, vy);
    __half2 q1 = __floats2half2_rn(vz, vw);
    uint2 pk;
    pk.x = *(unsigned*)&q0;
    pk.y = *(unsigned*)&q1;
    ((uint2*)g_a1h)[t * 32 + lane] = pk;
}

// ---------------- K4: h2 = a1h @ W2 via fp16 mma.sync (64-row block) ---------
// 8 warps: rows (warp&3)*16..+15, cols (warp>>2)*16..+15. A = a1h fp16 copied
// raw; B = W2 transposed to [n][k] fp16. 26 KB smem.
__global__ void __launch_bounds__(256) k_gemm2(
    const float* __restrict__ W2, const float* __restrict__ a_s,
    const float* __restrict__ a_d, int N) {
    extern __shared__ __half smh[];
    __half* As = smh;                 // [64][AS2] fp16  (17408 B)
    __half* Bs = smh + 64 * AS2;      // [32][BS2] fp16  (8704 B)
    int tid  = threadIdx.x;
    int row0 = blockIdx.x * 64;

    // stage A: raw fp16 copy, 64 rows x 128 halves = 1024 uint4
#pragma unroll
    for (int i = 0; i < 4; i++) {
        int lin = i * 256 + tid;
        int r = lin >> 4, k8 = lin & 15;        // 8 halves per uint4
        int row = row0 + r;
        uint4 v = make_uint4(0u, 0u, 0u, 0u);
        if (row < N) v = ((const uint4*)g_a1h)[row * 16 + k8];
        *(uint4*)(As + r * AS2 + k8 * 8) = v;
    }
    // stage B: W2 [k][n] fp32 -> Bs[n][k] fp16 (transpose)
#pragma unroll
    for (int jj = 0; jj < 16; jj++) {
        int idx = jj * 256 + tid;               // 4096 elements
        int k = idx >> 5, n = idx & 31;
        Bs[n * BS2 + k] = __float2half(W2[k * D + n]);
    }
    __syncthreads();

    int lane = tid & 31, warp = tid >> 5;
    int g = lane >> 2, t4 = lane & 3;
    int rw16 = (warp & 3) * 16;
    int nh   = (warp >> 2) * 16;

    float c[2][4];
    c[0][0] = c[0][1] = c[0][2] = c[0][3] = 0.f;
    c[1][0] = c[1][1] = c[1][2] = c[1][3] = 0.f;

#pragma unroll
    for (int k0 = 0; k0 < 128; k0 += 16) {
        unsigned a0 = *(const unsigned*)(As + (rw16 + g)     * AS2 + k0 + t4 * 2);
        unsigned a1 = *(const unsigned*)(As + (rw16 + g + 8) * AS2 + k0 + t4 * 2);
        unsigned a2 = *(const unsigned*)(As + (rw16 + g)     * AS2 + k0 + 8 + t4 * 2);
        unsigned a3 = *(const unsigned*)(As + (rw16 + g + 8) * AS2 + k0 + 8 + t4 * 2);
#pragma unroll
        for (int n = 0; n < 2; n++) {
            int nc = nh + n * 8 + g;
            unsigned b0 = *(const unsigned*)(Bs + nc * BS2 + k0 + t4 * 2);
            unsigned b1 = *(const unsigned*)(Bs + nc * BS2 + k0 + 8 + t4 * 2);
            mma_f16(c[n], a0, a1, a2, a3, b0, b1);
        }
    }
    __syncthreads();                 // done reading As/Bs

    float* Cs = (float*)smh;         // reuse as [64][CS2] fp32 (9216 B)
#pragma unroll
    for (int n = 0; n < 2; n++) {
        int col = nh + n * 8 + t4 * 2;
        *(float2*)(Cs + (rw16 + g)     * CS2 + col) = make_float2(c[n][0], c[n][1]);
        *(float2*)(Cs + (rw16 + g + 8) * CS2 + col) = make_float2(c[n][2], c[n][3]);
    }
    __syncthreads();

    // epilogue: warp w2 covers rows w2*8..+7, lane = col
    int w2 = tid >> 5;
    float sa = a_s[lane], da = a_d[lane];
#pragma unroll
    for (int i = 0; i < 8; i++) {
        int r   = w2 * 8 + i;
        int row = row0 + r;
        float v = Cs[r * CS2 + lane];
        float ps = warp_sum(v * sa);
        float pd = warp_sum(v * da);
        if (row < N) {
            g_h2h[row * D + lane] = __float2half(v);
            if (lane == 0) { g_as2[row] = ps; g_ad2[row] = pd; }
        }
    }
}

// ---------------- K5: layer-2 gather-aggregate + fused rating projection -----
__global__ void __launch_bounds__(256) k_agg2(
    const float* __restrict__ b2, const float* __restrict__ Wp, int N) {
    __shared__ float exs[8][CAP];   // 4 KB
    int warp = threadIdx.x >> 5, lane = threadIdx.x & 31;
    int t = blockIdx.x * 8 + warp;
    if (t >= N) return;
    float adt = g_ad2[t];
    int   deg = min(g_cnt[t], CAP);
    const int* cl = g_col + t * CAP;

    for (int j0 = 0; j0 < deg; j0 += 32) {
        int idx = j0 + lane;
        if (idx < deg) {
            int sp = cl[idx];
            exs[warp][idx] = __expf(lrelu(g_as2[sp >> 5] + adt));
        }
    }
    __syncwarp();

    const float* eh = exs[warp];
    float acc = 0.f, sum = 0.f;
    int j = 0;
    for (; j + 4 <= deg; j += 4) {
        int4   ss = *(const int4*)(cl + j);
        float4 ev = *(const float4*)(eh + j);
        float h0 = __half2float(g_h2h[ss.x + lane]);
        float h1 = __half2float(g_h2h[ss.y + lane]);
        float h2 = __half2float(g_h2h[ss.z + lane]);
        float h3 = __half2float(g_h2h[ss.w + lane]);
        acc += ev.x * h0 + ev.y * h1 + ev.z * h2 + ev.w * h3;
        sum += (ev.x + ev.y) + (ev.z + ev.w);
    }
    for (; j < deg; j++) {
        int   sp = cl[j];
        float e0 = eh[j];
        acc += e0 * __half2float(g_h2h[sp + lane]);
        sum += e0;
    }
    float v = acc * __fdividef(1.f, sum + 1e-16f) + b2[lane];
    float ps = warp_sum(v * Wp[lane]);
    float pt = warp_sum(v * Wp[D + lane]);
    if (lane == 0) { g_ps[t] = ps; g_pt[t] = pt; }
}

// ---------------- K6: edge rating = ps[src] + pt[dst] + bp (thread/edge) -----
__global__ void __launch_bounds__(256) k_pred(
    const int* __restrict__ ei, const float* __restrict__ bp,
    float* __restrict__ out, int E) {
    int e = blockIdx.x * blockDim.x + threadIdx.x;
    if (e >= E) return;
    int s = __ldg(ei + e), t = __ldg(ei + E + e);
    out[e] = g_ps[s] + g_pt[t] + bp[0];
}

// ---------------- launch ----------------
extern "C" void kernel_launch(void* const* d_in, const int* in_sizes, int n_in,
                              void* d_out, int out_size) {
    const float* x   = (const float*)d_in[0];
    const int*   ei  = (const int*)  d_in[1];
    const float* W1  = (const float*)d_in[2];
    const float* as1 = (const float*)d_in[3];
    const float* ad1 = (const float*)d_in[4];
    const float* b1  = (const float*)d_in[5];
    const float* W2  = (const float*)d_in[6];
    const float* as2 = (const float*)d_in[7];
    const float* ad2 = (const float*)d_in[8];
    const float* b2  = (const float*)d_in[9];
    const float* Wp  = (const float*)d_in[10];
    const float* bp  = (const float*)d_in[11];
    float*       out = (float*)d_out;

    int N  = in_sizes[0] / F;
    int E  = in_sizes[1] / 2;
    int Et = E + N;
    if (N > NMAX) return;

    int smem1 = 2 * 128 * XT * (int)sizeof(unsigned);           // 139264
    int smem2 = (64 * AS2 + 32 * BS2) * (int)sizeof(__half);    // 26112
    cudaFuncSetAttribute(k_gemm1, cudaFuncAttributeMaxDynamicSharedMemorySize, smem1);
    cudaFuncSetAttribute(k_gemm2, cudaFuncAttributeMaxDynamicSharedMemorySize, smem2);

    k_gemm1  <<<(N + 127) / 128, 256, smem1>>>(x, W1, as1, ad1, N);  // also zeroes g_cnt
    k_scatter<<<(Et + 255) / 256, 256>>>(ei, E, N);
    k_agg1   <<<(N + 7) / 8, 256>>>(b1, N);
    k_gemm2  <<<(N + 63) / 64, 256, smem2>>>(W2, as2, ad2, N);
    k_agg2   <<<(N + 7) / 8, 256>>>(b2, Wp, N);
    k_pred   <<<(E + 255) / 256, 256>>>(ei, bp, out, E);
}